// round 1
// baseline (speedup 1.0000x reference)
#include <cuda_runtime.h>
#include <math.h>

#define BB 256
#define SS 256
#define HH 512
#define INF 512
#define XROW 514   // IN + 2

// Scratch (device globals; no runtime allocation allowed)
__device__ float g_G[(size_t)SS * 8 * BB * HH];   // [s][gate][b][h]  pre-activations, 1 GiB
__device__ float g_h[2][BB * HH];                 // ping-pong hidden state
__device__ float g_c[BB * HH];                    // cell state (in-place)

__device__ __forceinline__ float sigf(float x) { return 1.0f / (1.0f + expf(-x)); }

struct ProjArgs {
    const float* x;          // lstm_input (B,S,514)
    const float* Wx[8];      // (512,512) each
    const float* bias[8];    // (512,)
    const float* aux1[8];    // Wt1/Wt2/Wd1/Wd2/Wto (512,) or null
    const float* aux2[8];    // Wdo for gate 7
};

// ---------------------------------------------------------------------------
// Projection GEMM: G[s][g][b][h] = x[b,s,:] @ Wx_g  + gate-specific extras
// grid = (N/64, M/64, 8 gates), block = 256 threads, 64x64 tile, 4x4/thread
// ---------------------------------------------------------------------------
__global__ void proj_kernel(ProjArgs p) {
    const int g  = blockIdx.z;
    const int m0 = blockIdx.y * 64;      // m = b*S + s
    const int n0 = blockIdx.x * 64;      // h

    __shared__ float As[64][17];         // [m][k] padded
    __shared__ float Bs[16][64];         // [k][h]

    const int tid = threadIdx.x;
    const int tm = tid >> 4;             // 0..15
    const int tn = tid & 15;             // 0..15

    const float* W = p.Wx[g];

    float acc[4][4] = {};

    for (int k0 = 0; k0 < INF; k0 += 16) {
        // Load A: x rows are contiguous in k (row stride 514, offset 2)
        #pragma unroll
        for (int q = 0; q < 4; q++) {
            int m = q * 16 + (tid >> 4);
            int kk = tid & 15;
            As[m][kk] = p.x[(size_t)(m0 + m) * XROW + 2 + k0 + kk];
        }
        // Load B (weights): float4 coalesced
        {
            int idx = tid * 4;
            int kk = idx >> 6;
            int hc = idx & 63;
            float4 w = *(const float4*)&W[(size_t)(k0 + kk) * HH + n0 + hc];
            *(float4*)&Bs[kk][hc] = w;
        }
        __syncthreads();

        #pragma unroll
        for (int kk = 0; kk < 16; kk++) {
            float a0 = As[tm * 4 + 0][kk];
            float a1 = As[tm * 4 + 1][kk];
            float a2 = As[tm * 4 + 2][kk];
            float a3 = As[tm * 4 + 3][kk];
            float4 b = *(const float4*)&Bs[kk][tn * 4];
            acc[0][0] += a0 * b.x; acc[0][1] += a0 * b.y; acc[0][2] += a0 * b.z; acc[0][3] += a0 * b.w;
            acc[1][0] += a1 * b.x; acc[1][1] += a1 * b.y; acc[1][2] += a1 * b.z; acc[1][3] += a1 * b.w;
            acc[2][0] += a2 * b.x; acc[2][1] += a2 * b.y; acc[2][2] += a2 * b.z; acc[2][3] += a2 * b.w;
            acc[3][0] += a3 * b.x; acc[3][1] += a3 * b.y; acc[3][2] += a3 * b.z; acc[3][3] += a3 * b.w;
        }
        __syncthreads();
    }

    // Epilogue: add bias + gate-specific terms, scatter to G[s][g][b][h]
    const float* bias = p.bias[g];
    const float* a1p = p.aux1[g];
    const float* a2p = p.aux2[g];

    #pragma unroll
    for (int i = 0; i < 4; i++) {
        int m = m0 + tm * 4 + i;
        int bidx = m / SS;
        int sidx = m % SS;
        float Tt = p.x[(size_t)m * XROW + 0];
        float Dt = p.x[(size_t)m * XROW + 1];
        size_t base = (((size_t)sidx * 8 + g) * BB + bidx) * HH;
        #pragma unroll
        for (int j = 0; j < 4; j++) {
            int h = n0 + tn * 4 + j;
            float v = acc[i][j] + bias[h];
            if (g == 3 || g == 4)       v += sigf(Tt * a1p[h]);
            else if (g == 5 || g == 6)  v += sigf(Dt * a1p[h]);
            else if (g == 7)            v += Tt * a1p[h] + Dt * a2p[h];
            g_G[base + h] = v;
        }
    }
}

// ---------------------------------------------------------------------------
// Recurrence step: Y_g = h_prev @ Wh_g (4 gates), fused cell update.
// grid = (B/32, H/32) = (8,16), block = 256. Thread: 1 b-row, 4 h-cols, 4 gates
// ---------------------------------------------------------------------------
__global__ void step_kernel(const float* __restrict__ Whi,
                            const float* __restrict__ Whf,
                            const float* __restrict__ Whc,
                            const float* __restrict__ Who,
                            float* __restrict__ hidden_out, int t) {
    const float* hprev = g_h[t & 1];
    float* hnext = g_h[(t + 1) & 1];

    const int b0 = blockIdx.x * 32;
    const int h0 = blockIdx.y * 32;

    __shared__ float As[32][33];          // [b][k] padded
    __shared__ float Ws[4][32][32];       // [gate][k][h]

    const int tid = threadIdx.x;
    const int bl = tid >> 3;              // 0..31
    const int hq = tid & 7;               // 0..7  -> h cols hq*4..hq*4+3

    const float* Wg[4] = {Whi, Whf, Whc, Who};

    float acc[4][4] = {};

    for (int k0 = 0; k0 < HH; k0 += 32) {
        // A tile: 32 rows x 32 k; one float4 per thread
        {
            int r = tid >> 3;
            int kc = (tid & 7) * 4;
            float4 av = *(const float4*)&hprev[(size_t)(b0 + r) * HH + k0 + kc];
            As[r][kc + 0] = av.x; As[r][kc + 1] = av.y;
            As[r][kc + 2] = av.z; As[r][kc + 3] = av.w;
        }
        // W tiles: 4 gates x 32k x 32h; one float4 per gate per thread
        {
            int kk = tid >> 3;
            int hc = (tid & 7) * 4;
            #pragma unroll
            for (int g = 0; g < 4; g++) {
                float4 w = *(const float4*)&Wg[g][(size_t)(k0 + kk) * HH + h0 + hc];
                *(float4*)&Ws[g][kk][hc] = w;
            }
        }
        __syncthreads();

        #pragma unroll
        for (int kk = 0; kk < 32; kk++) {
            float a = As[bl][kk];
            #pragma unroll
            for (int g = 0; g < 4; g++) {
                float4 w = *(const float4*)&Ws[g][kk][hq * 4];
                acc[g][0] += a * w.x; acc[g][1] += a * w.y;
                acc[g][2] += a * w.z; acc[g][3] += a * w.w;
            }
        }
        __syncthreads();
    }

    // Fused pointwise cell update
    const int b = b0 + bl;
    const size_t gstep = (size_t)t * 8 * BB * HH;
    #pragma unroll
    for (int j = 0; j < 4; j++) {
        int h = h0 + hq * 4 + j;
        size_t bh = (size_t)b * HH + h;
        float xi = g_G[gstep + (size_t)0 * BB * HH + bh] + acc[0][j];
        float xf = g_G[gstep + (size_t)1 * BB * HH + bh] + acc[1][j];
        float xc = g_G[gstep + (size_t)2 * BB * HH + bh] + acc[2][j];
        float t1 = g_G[gstep + (size_t)3 * BB * HH + bh];
        float t2 = g_G[gstep + (size_t)4 * BB * HH + bh];
        float d1 = g_G[gstep + (size_t)5 * BB * HH + bh];
        float d2 = g_G[gstep + (size_t)6 * BB * HH + bh];
        float o  = g_G[gstep + (size_t)7 * BB * HH + bh] + acc[3][j];

        float it = sigf(xi);
        float ft = sigf(xf);
        float jj = tanhf(xc);
        float T1 = sigf(t1), T2 = sigf(t2), D1 = sigf(d1), D2 = sigf(d2);
        float c = g_c[bh];
        float chat = ft * c + it * T1 * D1 * jj;
        float cnew = ft * c + it * T2 * D2 * jj;
        float ot = sigf(o);
        float hn = ot * tanhf(chat);

        g_c[bh] = cnew;
        hnext[bh] = hn;
        hidden_out[((size_t)b * SS + t) * HH + h] = hn;
    }
}

__global__ void init_kernel() {
    int i = blockIdx.x * blockDim.x + threadIdx.x;
    if (i < BB * HH) {
        g_h[0][i] = 0.0f;
        g_c[i] = 0.0f;
    }
}

__global__ void tail_kernel(float* __restrict__ out, size_t out_size) {
    int i = blockIdx.x * blockDim.x + threadIdx.x;
    if (i < BB * HH) {
        size_t base = (size_t)BB * SS * HH;
        if (base + i < out_size)                out[base + i] = g_h[0][i];          // h_t (after t=255 -> buf 0)
        if (base + (size_t)BB * HH + i < out_size) out[base + (size_t)BB * HH + i] = g_c[i];  // c_t
    }
}

extern "C" void kernel_launch(void* const* d_in, const int* in_sizes, int n_in,
                              void* d_out, int out_size) {
    const float* x = (const float*)d_in[0];

    ProjArgs pa = {};
    pa.x = x;
    pa.Wx[0] = (const float*)d_in[1];  pa.bias[0] = (const float*)d_in[3];
    pa.Wx[1] = (const float*)d_in[4];  pa.bias[1] = (const float*)d_in[6];
    pa.Wx[2] = (const float*)d_in[7];  pa.bias[2] = (const float*)d_in[9];
    pa.Wx[3] = (const float*)d_in[10]; pa.aux1[3] = (const float*)d_in[11]; pa.bias[3] = (const float*)d_in[12];
    pa.Wx[4] = (const float*)d_in[13]; pa.aux1[4] = (const float*)d_in[14]; pa.bias[4] = (const float*)d_in[15];
    pa.Wx[5] = (const float*)d_in[16]; pa.aux1[5] = (const float*)d_in[17]; pa.bias[5] = (const float*)d_in[18];
    pa.Wx[6] = (const float*)d_in[19]; pa.aux1[6] = (const float*)d_in[20]; pa.bias[6] = (const float*)d_in[21];
    pa.Wx[7] = (const float*)d_in[22]; pa.aux1[7] = (const float*)d_in[24]; pa.aux2[7] = (const float*)d_in[25];
    pa.bias[7] = (const float*)d_in[26];

    const float* Whi = (const float*)d_in[2];
    const float* Whf = (const float*)d_in[5];
    const float* Whc = (const float*)d_in[8];
    const float* Who = (const float*)d_in[23];

    float* out = (float*)d_out;

    init_kernel<<<(BB * HH + 255) / 256, 256>>>();

    dim3 pgrid(HH / 64, (BB * SS) / 64, 8);
    proj_kernel<<<pgrid, 256>>>(pa);

    dim3 sgrid(BB / 32, HH / 32);
    for (int t = 0; t < SS; t++) {
        step_kernel<<<sgrid, 256>>>(Whi, Whf, Whc, Who, out, t);
    }

    tail_kernel<<<(BB * HH + 255) / 256, 256>>>(out, (size_t)out_size);
}